// round 14
// baseline (speedup 1.0000x reference)
#include <cuda_runtime.h>
#include <math.h>
#include <stdint.h>

// Problem constants
#define Bq   8
#define Cc   64
#define Hh   256
#define Ww   256
#define HWs  65536        // H*W
#define CHW  4194304      // C*H*W
#define RB   16           // CTAs per batch
#define T_W  16           // w columns per CTA
#define GROUPS 16         // cout groups (4 couts each)
#define THREADS 256
#define RSTR 20           // smem floats per channel row: [0]=halo, [1..16]=data, [17]=halo, pad

#define W_SMEM_F4  (Cc * GROUPS * 3)        // 3072 float4, [cin][g][tap]
#define W_FLOATS   (W_SMEM_F4 * 4)          // 12288 floats
#define ROWBUF_FLOATS (Cc * RSTR)           // 1280 floats per buffer
#define SMEM_BYTES ((W_FLOATS + 2 * ROWBUF_FLOATS) * 4)   // 59392

// halo slot: [b][r][side][parity][g] as float4 (couts 4g..4g+3)
// side 0 = CTA r's leftmost column, side 1 = rightmost
__device__ float4       g_halo4[Bq][RB][2][2][GROUPS];
// monotonic "rows published" counter per CTA; +256 per launch, uniform across CTAs
__device__ unsigned int g_flag[Bq][RB];

// ---------------- scoped-model primitives (no membars, no volatile) ----------------
__device__ __forceinline__ void st_release_u32(unsigned int* p, unsigned int v) {
    asm volatile("st.release.gpu.global.u32 [%0], %1;" :: "l"(p), "r"(v) : "memory");
}
__device__ __forceinline__ unsigned int ld_acquire_u32(const unsigned int* p) {
    unsigned int v;
    asm volatile("ld.acquire.gpu.global.u32 %0, [%1];" : "=r"(v) : "l"(p) : "memory");
    return v;
}
__device__ __forceinline__ float4 ld_relaxed_v4(const float4* p) {
    float4 v;
    asm volatile("ld.relaxed.gpu.global.v4.f32 {%0,%1,%2,%3}, [%4];"
                 : "=f"(v.x), "=f"(v.y), "=f"(v.z), "=f"(v.w) : "l"(p) : "memory");
    return v;
}
__device__ __forceinline__ unsigned int ld_relaxed_u32(const unsigned int* p) {
    unsigned int v;
    asm volatile("ld.relaxed.gpu.global.u32 %0, [%1];" : "=r"(v) : "l"(p) : "memory");
    return v;
}

// MUFU-free tanh (proven R10): FFMA-only exp2 + Newton reciprocal, abs err ~1e-6
__device__ __forceinline__ float tanh_fast(float x) {
    float t = fminf(2.0f * fabsf(x), 24.0f);
    float s = t * 1.4426950408889634f;
    float kf = s + 12582912.0f;
    int   n  = __float_as_int(kf) - 0x4B400000;
    float f  = s - (kf - 12582912.0f);
    float p = 1.5423431e-4f;
    p = fmaf(p, f, 1.3333558e-3f);
    p = fmaf(p, f, 9.6181291e-3f);
    p = fmaf(p, f, 5.5504109e-2f);
    p = fmaf(p, f, 2.4022651e-1f);
    p = fmaf(p, f, 6.9314718e-1f);
    p = fmaf(p, f, 1.0f);
    float e = __int_as_float(__float_as_int(p) + (n << 23));
    float u = e + 1.0f;
    float r = __int_as_float(0x7EF311C3 - __float_as_int(u));
    r = r * fmaf(-u, r, 2.0f);
    r = r * fmaf(-u, r, 2.0f);
    r = r * fmaf(-u, r, 2.0f);
    return copysignf(fmaf(-2.0f, r, 1.0f), x);
}

// poll neighbor flag (acquire), then fetch its edge column into row-buffer sentinels
__device__ __forceinline__ void fetch_halo(const unsigned int* nflag, unsigned int tgt,
                                           const float4* src, float* dst, int dof)
{
    while ((int)(ld_acquire_u32(nflag) - tgt) < 0) { }
#pragma unroll
    for (int i = 0; i < GROUPS; i++) {
        float4 v = ld_relaxed_v4(src + i);          // strong: L2-coherent, pipelined
        dst[(4 * i + 0) * RSTR + dof] = v.x;
        dst[(4 * i + 1) * RSTR + dof] = v.y;
        dst[(4 * i + 2) * RSTR + dof] = v.z;
        dst[(4 * i + 3) * RSTR + dof] = v.w;
    }
}

__global__ void __launch_bounds__(THREADS, 1)
spatial_conv_kernel(const float* __restrict__ X,
                    const float* __restrict__ Wc,   // [64][64][3]
                    const float* __restrict__ bc,   // [64]
                    float* __restrict__ Y)
{
    extern __shared__ float smem[];
    float4* wS4 = reinterpret_cast<float4*>(smem);      // [cin][g][tap]
    float*  d0  = smem + W_FLOATS;                      // row buffer A
    float*  d1  = d0 + ROWBUF_FLOATS;                   // row buffer B

    const int tid = threadIdx.x;
    const int b   = blockIdx.x >> 4;
    const int r   = blockIdx.x & 15;
    const int w   = tid & 15;
    const int g   = tid >> 4;
    const int c0  = g * 4;
    const int wg  = r * T_W + w;

    // ---- stage weights: wS4[(cin*16 + g)*3 + tap] ----
    for (int idx = tid; idx < W_SMEM_F4; idx += THREADS) {
        int cin = idx / 48;
        int rem = idx - cin * 48;
        int gg  = rem / 3;
        int tap = rem - gg * 3;
        float4 v;
        v.x = Wc[((4 * gg + 0) * Cc + cin) * 3 + tap];
        v.y = Wc[((4 * gg + 1) * Cc + cin) * 3 + tap];
        v.z = Wc[((4 * gg + 2) * Cc + cin) * 3 + tap];
        v.w = Wc[((4 * gg + 3) * Cc + cin) * 3 + tap];
        wS4[idx] = v;
    }
    // zero sentinels in BOTH buffers (edge CTAs keep missing side zero forever)
    for (int c = tid; c < Cc; c += THREADS) {
        d0[c * RSTR + 0] = 0.0f; d0[c * RSTR + 17] = 0.0f;
        d1[c * RSTR + 0] = 0.0f; d1[c * RSTR + 17] = 0.0f;
    }

    const float bz0 = bc[c0 + 0];
    const float bz1 = bc[c0 + 1];
    const float bz2 = bc[c0 + 2];
    const float bz3 = bc[c0 + 3];

    unsigned int base = 0;
    if (tid < 2) base = ld_relaxed_u32(&g_flag[b][r]);

    const float* Xb = X + b * CHW;
    float*       Yb = Y + b * CHW;

    // ---- row 0: Y[0] = X[0] ----
    {
        float y0 = Xb[(c0 + 0) * HWs + wg];
        float y1 = Xb[(c0 + 1) * HWs + wg];
        float y2 = Xb[(c0 + 2) * HWs + wg];
        float y3 = Xb[(c0 + 3) * HWs + wg];
        Yb[(c0 + 0) * HWs + wg] = y0;
        Yb[(c0 + 1) * HWs + wg] = y1;
        Yb[(c0 + 2) * HWs + wg] = y2;
        Yb[(c0 + 3) * HWs + wg] = y3;
        d0[(c0 + 0) * RSTR + 1 + w] = y0;
        d0[(c0 + 1) * RSTR + 1 + w] = y1;
        d0[(c0 + 2) * RSTR + 1 + w] = y2;
        d0[(c0 + 3) * RSTR + 1 + w] = y3;
        if (w == 0)  g_halo4[b][r][0][0][g] = make_float4(y0, y1, y2, y3);
        if (w == 15) g_halo4[b][r][1][0][g] = make_float4(y0, y1, y2, y3);
    }
    __syncthreads();
    if (tid == 0) {
        st_release_u32(&g_flag[b][r], base + 1u);
        if (r > 0)
            fetch_halo(&g_flag[b][r - 1], base + 1u, &g_halo4[b][r - 1][1][0][0], d0, 0);
    } else if (tid == 1) {
        if (r < 15)
            fetch_halo(&g_flag[b][r + 1], base + 1u, &g_halo4[b][r + 1][0][0][0], d0, 17);
    }
    __syncthreads();

    // ---- recurrence ----
    for (int h = 1; h < Hh; h++) {
        float* rd = ((h - 1) & 1) ? d1 : d0;    // row h-1 (+ its halos)
        float* wr = (h & 1) ? d1 : d0;          // row h target

        // prefetch X for this row's outputs (hidden under the conv)
        const float* xrow = Xb + h * Ww + wg;
        float xi0 = xrow[(c0 + 0) * HWs];
        float xi1 = xrow[(c0 + 1) * HWs];
        float xi2 = xrow[(c0 + 2) * HWs];
        float xi3 = xrow[(c0 + 3) * HWs];

        float a0 = bz0, a1 = bz1, a2 = bz2, a3 = bz3;

        const float*  xp = rd + w;            // [0]=w-1, [1]=w, [2]=w+1
        const float4* wp = wS4 + g * 3;       // [cin][g][tap], stride 48 per cin
#pragma unroll 8
        for (int cin = 0; cin < Cc; cin++) {
            float xl = xp[0];
            float xc = xp[1];
            float xr = xp[2];
            float4 K0 = wp[0];
            float4 K1 = wp[1];
            float4 K2 = wp[2];
            a0 = fmaf(K0.x, xl, a0); a0 = fmaf(K1.x, xc, a0); a0 = fmaf(K2.x, xr, a0);
            a1 = fmaf(K0.y, xl, a1); a1 = fmaf(K1.y, xc, a1); a1 = fmaf(K2.y, xr, a1);
            a2 = fmaf(K0.z, xl, a2); a2 = fmaf(K1.z, xc, a2); a2 = fmaf(K2.z, xr, a2);
            a3 = fmaf(K0.w, xl, a3); a3 = fmaf(K1.w, xc, a3); a3 = fmaf(K2.w, xr, a3);
            xp += RSTR;
            wp += 48;
        }

        float y0 = xi0 + tanh_fast(a0);
        float y1 = xi1 + tanh_fast(a1);
        float y2 = xi2 + tanh_fast(a2);
        float y3 = xi3 + tanh_fast(a3);

        float* yrow = Yb + h * Ww + wg;
        yrow[(c0 + 0) * HWs] = y0;
        yrow[(c0 + 1) * HWs] = y1;
        yrow[(c0 + 2) * HWs] = y2;
        yrow[(c0 + 3) * HWs] = y3;

        if (h == Hh - 1) {
            if (tid == 0) st_release_u32(&g_flag[b][r], base + 256u);  // launch invariant
            break;
        }

        // write row h into the other buffer (no hazard with rd) + publish edges
        wr[(c0 + 0) * RSTR + 1 + w] = y0;
        wr[(c0 + 1) * RSTR + 1 + w] = y1;
        wr[(c0 + 2) * RSTR + 1 + w] = y2;
        wr[(c0 + 3) * RSTR + 1 + w] = y3;
        const int par = h & 1;
        if (w == 0)  g_halo4[b][r][0][par][g] = make_float4(y0, y1, y2, y3);
        if (w == 15) g_halo4[b][r][1][par][g] = make_float4(y0, y1, y2, y3);

        __syncthreads();   // (A) edge publishes + wr stores visible CTA-wide

        if (tid == 0) {
            st_release_u32(&g_flag[b][r], base + (unsigned)h + 1u);  // bar-cumulative release
            if (r > 0)
                fetch_halo(&g_flag[b][r - 1], base + (unsigned)h + 1u,
                           &g_halo4[b][r - 1][1][par][0], wr, 0);
        } else if (tid == 1) {
            if (r < 15)
                fetch_halo(&g_flag[b][r + 1], base + (unsigned)h + 1u,
                           &g_halo4[b][r + 1][0][par][0], wr, 17);
        }

        __syncthreads();   // (B) halos landed in wr sentinels
    }
}

extern "C" void kernel_launch(void* const* d_in, const int* in_sizes, int n_in,
                              void* d_out, int out_size)
{
    const float* X  = (const float*)d_in[0];
    const float* Wc = (const float*)d_in[1];
    const float* bc = (const float*)d_in[2];
    float*       Y  = (float*)d_out;
    (void)in_sizes; (void)n_in; (void)out_size;

    cudaFuncSetAttribute(spatial_conv_kernel,
                         cudaFuncAttributeMaxDynamicSharedMemorySize, SMEM_BYTES);

    spatial_conv_kernel<<<Bq * RB, THREADS, SMEM_BYTES>>>(X, Wc, bc, Y);
}